// round 15
// baseline (speedup 1.0000x reference)
#include <cuda_runtime.h>
#include <cuda_fp16.h>
#include <math.h>

#define NN 150000
#define NE 1250000
#define NG 4096
#define HID 64

#define PS_B 512
#define PS_NB ((NN + PS_B - 1) / PS_B)   // 293

// Scratch (__device__ globals; no allocation allowed)
__device__ __align__(256) float  g_dinv[NN];
__device__ __align__(256) float2 g_xs[NN];        // x' = x * dinv (pre-scaled input)
__device__ __align__(256) int    g_indeg[NN];
__device__ __align__(256) int    g_off[NN + 1];   // global exclusive offsets
__device__ __align__(256) int    g_cursor[NN];
__device__ __align__(256) int    g_bsum[PS_NB];
__device__ __align__(256) int    g_edges[NE];     // src only (4B), bucketed by dst
__device__ __align__(256) __half g_T0[NN * HID];  // h' = h*dinv ping (fp16)
__device__ __align__(256) __half g_T1[NN * HID];  // h' pong (fp16)
__device__ __align__(256) float  g_pool[NG * HID];
__device__ __align__(256) float  g_cnt[NG];

__device__ __forceinline__ void red_add_v2(float* addr, float a, float b) {
    asm volatile("red.global.add.v2.f32 [%0], {%1,%2};"
                 :: "l"(addr), "f"(a), "f"(b) : "memory");
}

// ---------------- degree ----------------
__global__ void k_deg_accum(const int* __restrict__ ei) {
    int e = blockIdx.x * blockDim.x + threadIdx.x;
    if (e < NE) atomicAdd(&g_indeg[ei[NE + e]], 1);
}

// ---------------- CSR scan 1: local scan + dinv + x' precompute ----------------
__global__ void k_ps1(const float* __restrict__ x) {
    __shared__ int sh[PS_B];
    int tid = threadIdx.x;
    int i = blockIdx.x * PS_B + tid;
    int v = (i < NN) ? g_indeg[i] : 0;
    if (i < NN) {
        float di = rsqrtf((float)(v + 1));
        g_dinv[i] = di;
        float2 xv = *(const float2*)(x + 2 * i);
        g_xs[i] = make_float2(xv.x * di, xv.y * di);
    }
    sh[tid] = v;
    __syncthreads();
    for (int o = 1; o < PS_B; o <<= 1) {
        int t2 = (tid >= o) ? sh[tid - o] : 0;
        __syncthreads();
        sh[tid] += t2;
        __syncthreads();
    }
    if (i < NN) g_off[i] = sh[tid] - v;            // local exclusive
    if (tid == PS_B - 1) g_bsum[blockIdx.x] = sh[tid];
}
__global__ void k_ps2() {
    __shared__ int sh[PS_B];
    int tid = threadIdx.x;
    int v = (tid < PS_NB) ? g_bsum[tid] : 0;
    sh[tid] = v;
    __syncthreads();
    for (int o = 1; o < PS_B; o <<= 1) {
        int t2 = (tid >= o) ? sh[tid - o] : 0;
        __syncthreads();
        sh[tid] += t2;
        __syncthreads();
    }
    if (tid < PS_NB) g_bsum[tid] = sh[tid] - v;    // exclusive block offsets
}
// ps3: finalize offsets + zero pool/cnt (absorbs two memsets)
__global__ void k_ps3() {
    int i = blockIdx.x * PS_B + threadIdx.x;
    if (i < NN) {
        int o = g_off[i] + g_bsum[blockIdx.x];
        g_off[i] = o;
        g_cursor[i] = o;
    }
    if (i == 0) g_off[NN] = NE;
    for (int j = i; j < NG * HID; j += PS_NB * PS_B) g_pool[j] = 0.f;
    if (i < NG) g_cnt[i] = 0.f;
}
// ---------------- bucket fill: src only ----------------
__global__ void k_fill(const int* __restrict__ ei) {
    int e = blockIdx.x * blockDim.x + threadIdx.x;
    if (e >= NE) return;
    int s = ei[e];
    int d = ei[NE + e];
    int pos = atomicAdd(&g_cursor[d], 1);
    g_edges[pos] = s;
}

// ---------------- store 4 fp32 as 4 fp16 (8B) ----------------
__device__ __forceinline__ void store_h4(__half* dst, float4 v) {
    __half2 lo = __floats2half2_rn(v.x, v.y);
    __half2 hi = __floats2half2_rn(v.z, v.w);
    uint2 raw;
    raw.x = *(unsigned*)&lo;
    raw.y = *(unsigned*)&hi;
    *(uint2*)dst = raw;
}

// ---------------- layer 1: aggregate x' (2ch), fused W1+bias+relu, store h1*dinv ----------------
__global__ void k_aggr_x(const float* __restrict__ W1, const float* __restrict__ b1,
                         __half* __restrict__ hout) {
    __shared__ float W1s[2 * HID];
    __shared__ float b1s[HID];
    int tid = threadIdx.x;
    if (tid < 2 * HID) W1s[tid] = W1[tid];
    if (tid < HID) b1s[tid] = b1[tid];
    __syncthreads();
    int gt = blockIdx.x * blockDim.x + tid;
    int node = gt >> 4, q = gt & 15;
    if (node >= NN) return;
    int beg = __ldg(&g_off[node]), end = __ldg(&g_off[node + 1]);
    float s0 = 0.f, s1 = 0.f;
    int k = beg + q;
    for (; k + 48 < end; k += 64) {
        int p0 = __ldg(&g_edges[k]);
        int p1 = __ldg(&g_edges[k + 16]);
        int p2 = __ldg(&g_edges[k + 32]);
        int p3 = __ldg(&g_edges[k + 48]);
        float2 x0 = __ldg(&g_xs[p0]);
        float2 x1 = __ldg(&g_xs[p1]);
        float2 x2 = __ldg(&g_xs[p2]);
        float2 x3 = __ldg(&g_xs[p3]);
        s0 += x0.x + x1.x + x2.x + x3.x;
        s1 += x0.y + x1.y + x2.y + x3.y;
    }
    for (; k < end; k += 16) {
        float2 xv = __ldg(&g_xs[__ldg(&g_edges[k])]);
        s0 += xv.x; s1 += xv.y;
    }
#pragma unroll
    for (int o = 8; o; o >>= 1) {
        s0 += __shfl_xor_sync(0xffffffffu, s0, o, 16);
        s1 += __shfl_xor_sync(0xffffffffu, s1, o, 16);
    }
    float di = g_dinv[node];
    float2 xn = __ldg(&g_xs[node]);   // xn = x*di already
    // u = di*(S + x'[node])  =>  di*S + x*di^2
    s0 = di * (s0 + xn.x);
    s1 = di * (s1 + xn.y);
    int c0 = q * 4;
    float4 r;
    r.x = fmaxf(s0 * W1s[c0 + 0] + s1 * W1s[HID + c0 + 0] + b1s[c0 + 0], 0.f);
    r.y = fmaxf(s0 * W1s[c0 + 1] + s1 * W1s[HID + c0 + 1] + b1s[c0 + 1], 0.f);
    r.z = fmaxf(s0 * W1s[c0 + 2] + s1 * W1s[HID + c0 + 2] + b1s[c0 + 2], 0.f);
    r.w = fmaxf(s0 * W1s[c0 + 3] + s1 * W1s[HID + c0 + 3] + b1s[c0 + 3], 0.f);
    r.x *= di; r.y *= di; r.z *= di; r.w *= di;   // pre-scale for next layer
    store_h4(hout + (size_t)node * HID + c0, r);
}

// ---------------- warp-per-node aggregation: lane owns 2 fp16 channels ----------------
__device__ __forceinline__ float2 h2f(unsigned raw) {
    return __half22float2(*(__half2*)&raw);
}

#define ADD2(r) { float2 _v = h2f(r); acc.x += _v.x; acc.y += _v.y; }

// u = di*(sum t'[s] + t'[node]) for this lane's 2 channels.
__device__ __forceinline__ float2 agg_core_w(const __half* __restrict__ t, int node,
                                             int lane, float di) {
    const unsigned* tp = (const unsigned*)t;
    float2 acc = h2f(__ldg(tp + ((size_t)node << 5) + lane));   // t'[node]
    int beg = __ldg(&g_off[node]), end = __ldg(&g_off[node + 1]);
    int k = beg;
    for (; k + 8 <= end; k += 8) {
        int p0 = __ldg(&g_edges[k]);
        int p1 = __ldg(&g_edges[k + 1]);
        int p2 = __ldg(&g_edges[k + 2]);
        int p3 = __ldg(&g_edges[k + 3]);
        int p4 = __ldg(&g_edges[k + 4]);
        int p5 = __ldg(&g_edges[k + 5]);
        int p6 = __ldg(&g_edges[k + 6]);
        int p7 = __ldg(&g_edges[k + 7]);
        unsigned r0 = __ldg(tp + ((size_t)p0 << 5) + lane);
        unsigned r1 = __ldg(tp + ((size_t)p1 << 5) + lane);
        unsigned r2 = __ldg(tp + ((size_t)p2 << 5) + lane);
        unsigned r3 = __ldg(tp + ((size_t)p3 << 5) + lane);
        unsigned r4 = __ldg(tp + ((size_t)p4 << 5) + lane);
        unsigned r5 = __ldg(tp + ((size_t)p5 << 5) + lane);
        unsigned r6 = __ldg(tp + ((size_t)p6 << 5) + lane);
        unsigned r7 = __ldg(tp + ((size_t)p7 << 5) + lane);
        ADD2(r0); ADD2(r1); ADD2(r2); ADD2(r3);
        ADD2(r4); ADD2(r5); ADD2(r6); ADD2(r7);
    }
    if (k + 4 <= end) {
        int p0 = __ldg(&g_edges[k]);
        int p1 = __ldg(&g_edges[k + 1]);
        int p2 = __ldg(&g_edges[k + 2]);
        int p3 = __ldg(&g_edges[k + 3]);
        unsigned r0 = __ldg(tp + ((size_t)p0 << 5) + lane);
        unsigned r1 = __ldg(tp + ((size_t)p1 << 5) + lane);
        unsigned r2 = __ldg(tp + ((size_t)p2 << 5) + lane);
        unsigned r3 = __ldg(tp + ((size_t)p3 << 5) + lane);
        ADD2(r0); ADD2(r1); ADD2(r2); ADD2(r3);
        k += 4;
    }
    for (; k < end; k++) {
        unsigned r = __ldg(tp + ((size_t)__ldg(&g_edges[k]) << 5) + lane);
        ADD2(r);
    }
    acc.x *= di; acc.y *= di;
    return acc;
}

// Warp 64x64 matmul: lane holds channels {2*lane, 2*lane+1}; full-width shfl broadcast.
__device__ __forceinline__ float2 warp_matmul_w(float2 acc, const float* __restrict__ Ws,
                                                const float* __restrict__ bs, int lane) {
    float o0 = bs[2 * lane], o1 = bs[2 * lane + 1];
#pragma unroll
    for (int k = 0; k < HID; k++) {
        float hk = __shfl_sync(0xffffffffu, (k & 1) ? acc.y : acc.x, k >> 1, 32);
        float2 w = *(const float2*)&Ws[k * HID + 2 * lane];
        o0 += hk * w.x; o1 += hk * w.y;
    }
    o0 = fmaxf(o0, 0.f); o1 = fmaxf(o1, 0.f);
    return make_float2(o0, o1);
}

// ---------------- fused layer (warp per node) ----------------
__global__ void __launch_bounds__(512) k_layer(const __half* __restrict__ tin,
                                               const float* __restrict__ W,
                                               const float* __restrict__ b,
                                               __half* __restrict__ tout) {
    __shared__ float Ws[HID * HID];
    __shared__ float bs[HID];
    int tid = threadIdx.x;
    for (int i = tid; i < HID * HID; i += 512) Ws[i] = W[i];
    if (tid < HID) bs[tid] = b[tid];
    __syncthreads();
    int lane = tid & 31;
    int node = blockIdx.x * 16 + (tid >> 5);
    if (node >= NN) return;
    float di = g_dinv[node];
    float2 acc = agg_core_w(tin, node, lane, di);
    float2 o = warp_matmul_w(acc, Ws, bs, lane);
    o.x *= di; o.y *= di;   // pre-scale for next layer
    __half2 h = __floats2half2_rn(o.x, o.y);
    ((unsigned*)tout)[((size_t)node << 5) + lane] = *(unsigned*)&h;
}

// Layer-3 variant: plain h into the mean-pool accumulators.
__global__ void __launch_bounds__(512) k_layer_pool(const __half* __restrict__ tin,
                                                    const float* __restrict__ W,
                                                    const float* __restrict__ b,
                                                    const int* __restrict__ batch) {
    __shared__ float Ws[HID * HID];
    __shared__ float bs[HID];
    int tid = threadIdx.x;
    for (int i = tid; i < HID * HID; i += 512) Ws[i] = W[i];
    if (tid < HID) bs[tid] = b[tid];
    __syncthreads();
    int lane = tid & 31;
    int node = blockIdx.x * 16 + (tid >> 5);
    if (node >= NN) return;
    float di = g_dinv[node];
    float2 acc = agg_core_w(tin, node, lane, di);
    float2 o = warp_matmul_w(acc, Ws, bs, lane);
    int g = batch[node];
    red_add_v2(g_pool + (size_t)g * HID + 2 * lane, o.x, o.y);
    if (lane == 0) atomicAdd(&g_cnt[g], 1.0f);
}

// ---------------- per-graph MLP + sigmoid ----------------
__global__ void k_mlp(const float* __restrict__ lw1, const float* __restrict__ lb1,
                      const float* __restrict__ lw2, const float* __restrict__ lb2,
                      float* __restrict__ out) {
    __shared__ float w1s[HID * 32];
    __shared__ float b1s[32];
    __shared__ float w2s[32];
    int tid = threadIdx.x;
    for (int idx = tid; idx < HID * 32; idx += 128) w1s[idx] = lw1[idx];
    if (tid < 32) { b1s[tid] = lb1[tid]; w2s[tid] = lw2[tid]; }
    __syncthreads();
    int g = blockIdx.x * 128 + tid;
    if (g >= NG) return;
    float inv = 1.0f / fmaxf(g_cnt[g], 1.0f);
    float p[HID];
#pragma unroll
    for (int c = 0; c < HID; c++) p[c] = g_pool[g * HID + c] * inv;
    float z = lb2[0];
    for (int j = 0; j < 32; j++) {
        float a = b1s[j];
#pragma unroll
        for (int c = 0; c < HID; c++) a += p[c] * w1s[c * 32 + j];
        a = a > 0.f ? a : 0.f;
        z += a * w2s[j];
    }
    out[g] = 1.0f / (1.0f + expf(-z));
}

extern "C" void kernel_launch(void* const* d_in, const int* in_sizes, int n_in,
                              void* d_out, int out_size) {
    // Size-driven input identification (robust to metadata ordering).
    const float *x = 0, *W1 = 0, *b1 = 0, *W2 = 0, *b2 = 0, *W3 = 0, *b3 = 0;
    const float *lw1 = 0, *lb1 = 0, *lw2 = 0, *lb2 = 0;
    const int *ei = 0, *batch = 0;
    int nW = 0, nb = 0, n32 = 0;
    for (int i = 0; i < n_in; i++) {
        int sz = in_sizes[i];
        const void* p = d_in[i];
        switch (sz) {
            case 300000:  x = (const float*)p; break;
            case 2500000: ei = (const int*)p; break;
            case 150000:  batch = (const int*)p; break;
            case 128:     W1 = (const float*)p; break;
            case 4096:    if (nW++ == 0) W2 = (const float*)p; else W3 = (const float*)p; break;
            case 64:      if (nb == 0) b1 = (const float*)p;
                          else if (nb == 1) b2 = (const float*)p;
                          else b3 = (const float*)p;
                          nb++; break;
            case 2048:    lw1 = (const float*)p; break;
            case 32:      if (n32++ == 0) lb1 = (const float*)p; else lw2 = (const float*)p; break;
            case 1:       lb2 = (const float*)p; break;
        }
    }
    float* out = (float*)d_out;

    __half *gT0, *gT1;
    int *gIndeg;
    cudaGetSymbolAddress((void**)&gT0, g_T0);
    cudaGetSymbolAddress((void**)&gT1, g_T1);
    cudaGetSymbolAddress((void**)&gIndeg, g_indeg);

    const int TB = 256;
    // only indeg needs pre-zeroing (pool/cnt zeroed in ps3)
    cudaMemsetAsync(gIndeg, 0, NN * sizeof(int));

    // degree + CSR build (dst-bucketed, src-only records)
    k_deg_accum<<<(NE + TB - 1) / TB, TB>>>(ei);
    k_ps1 <<<PS_NB, PS_B>>>(x);
    k_ps2 <<<1, PS_B>>>();
    k_ps3 <<<PS_NB, PS_B>>>();
    k_fill<<<(NE + TB - 1) / TB, TB>>>(ei);

    // layer 1: aggregate x', fused W1+bias+relu -> h1' (fp16, pre-scaled)
    k_aggr_x<<<(NN * 16 + TB - 1) / TB, TB>>>(W1, b1, gT0);

    // layer 2 fused (warp per node)
    k_layer<<<(NN + 15) / 16, 512>>>(gT0, W2, b2, gT1);

    // layer 3 fused + pooled
    k_layer_pool<<<(NN + 15) / 16, 512>>>(gT1, W3, b3, batch);

    // MLP head
    k_mlp<<<(NG + 127) / 128, 128>>>(lw1, lb1, lw2, lb2, out);
}

// round 16
// speedup vs baseline: 1.1580x; 1.1580x over previous
#include <cuda_runtime.h>
#include <cuda_fp16.h>
#include <math.h>

#define NN 150000
#define NE 1250000
#define NG 4096
#define HID 64

#define PS_B 512
#define PS_NB ((NN + PS_B - 1) / PS_B)   // 293

// Scratch (__device__ globals; no allocation allowed)
__device__ __align__(256) float  g_dinv[NN];
__device__ __align__(256) float2 g_xs[NN];        // x' = x * dinv (pre-scaled input)
__device__ __align__(256) int    g_indeg[NN];
__device__ __align__(256) int    g_off[NN + 1];   // global exclusive offsets
__device__ __align__(256) int    g_cursor[NN];
__device__ __align__(256) int    g_bsum[PS_NB];
__device__ __align__(256) int    g_edges[NE];     // src only (4B), bucketed by dst
__device__ __align__(256) __half g_T0[NN * HID];  // h' = h*dinv ping (fp16)
__device__ __align__(256) __half g_T1[NN * HID];  // h' pong (fp16)
__device__ __align__(256) float  g_pool[NG * HID];
__device__ __align__(256) float  g_cnt[NG];

__device__ __forceinline__ void red_add_v4(float* addr, float4 v) {
    asm volatile("red.global.add.v4.f32 [%0], {%1,%2,%3,%4};"
                 :: "l"(addr), "f"(v.x), "f"(v.y), "f"(v.z), "f"(v.w)
                 : "memory");
}

// ---------------- degree ----------------
__global__ void k_deg_accum(const int* __restrict__ ei) {
    int e = blockIdx.x * blockDim.x + threadIdx.x;
    if (e < NE) atomicAdd(&g_indeg[ei[NE + e]], 1);
}

// ---------------- CSR scan 1: local scan + dinv + x' precompute ----------------
__global__ void k_ps1(const float* __restrict__ x) {
    __shared__ int sh[PS_B];
    int tid = threadIdx.x;
    int i = blockIdx.x * PS_B + tid;
    int v = (i < NN) ? g_indeg[i] : 0;
    if (i < NN) {
        float di = rsqrtf((float)(v + 1));
        g_dinv[i] = di;
        float2 xv = *(const float2*)(x + 2 * i);
        g_xs[i] = make_float2(xv.x * di, xv.y * di);
    }
    sh[tid] = v;
    __syncthreads();
    for (int o = 1; o < PS_B; o <<= 1) {
        int t2 = (tid >= o) ? sh[tid - o] : 0;
        __syncthreads();
        sh[tid] += t2;
        __syncthreads();
    }
    if (i < NN) g_off[i] = sh[tid] - v;            // local exclusive
    if (tid == PS_B - 1) g_bsum[blockIdx.x] = sh[tid];
}
__global__ void k_ps2() {
    __shared__ int sh[PS_B];
    int tid = threadIdx.x;
    int v = (tid < PS_NB) ? g_bsum[tid] : 0;
    sh[tid] = v;
    __syncthreads();
    for (int o = 1; o < PS_B; o <<= 1) {
        int t2 = (tid >= o) ? sh[tid - o] : 0;
        __syncthreads();
        sh[tid] += t2;
        __syncthreads();
    }
    if (tid < PS_NB) g_bsum[tid] = sh[tid] - v;    // exclusive block offsets
}
// ps3: finalize offsets + zero pool/cnt (absorbs two memsets)
__global__ void k_ps3() {
    int i = blockIdx.x * PS_B + threadIdx.x;
    if (i < NN) {
        int o = g_off[i] + g_bsum[blockIdx.x];
        g_off[i] = o;
        g_cursor[i] = o;
    }
    if (i == 0) g_off[NN] = NE;
    for (int j = i; j < NG * HID; j += PS_NB * PS_B) g_pool[j] = 0.f;
    if (i < NG) g_cnt[i] = 0.f;
}
// ---------------- bucket fill: src only ----------------
__global__ void k_fill(const int* __restrict__ ei) {
    int e = blockIdx.x * blockDim.x + threadIdx.x;
    if (e >= NE) return;
    int s = ei[e];
    int d = ei[NE + e];
    int pos = atomicAdd(&g_cursor[d], 1);
    g_edges[pos] = s;
}

// ---------------- store 4 fp32 as 4 fp16 (8B) ----------------
__device__ __forceinline__ void store_h4(__half* dst, float4 v) {
    __half2 lo = __floats2half2_rn(v.x, v.y);
    __half2 hi = __floats2half2_rn(v.z, v.w);
    uint2 raw;
    raw.x = *(unsigned*)&lo;
    raw.y = *(unsigned*)&hi;
    *(uint2*)dst = raw;
}

// ---------------- layer 1: aggregate x' (2ch), fused W1+bias+relu, store h1*dinv ----------------
__global__ void k_aggr_x(const float* __restrict__ W1, const float* __restrict__ b1,
                         __half* __restrict__ hout) {
    __shared__ float W1s[2 * HID];
    __shared__ float b1s[HID];
    int tid = threadIdx.x;
    if (tid < 2 * HID) W1s[tid] = W1[tid];
    if (tid < HID) b1s[tid] = b1[tid];
    __syncthreads();
    int gt = blockIdx.x * blockDim.x + tid;
    int node = gt >> 4, q = gt & 15;
    if (node >= NN) return;
    int beg = __ldg(&g_off[node]), end = __ldg(&g_off[node + 1]);
    float s0 = 0.f, s1 = 0.f;
    int k = beg + q;
    for (; k + 48 < end; k += 64) {
        int p0 = __ldg(&g_edges[k]);
        int p1 = __ldg(&g_edges[k + 16]);
        int p2 = __ldg(&g_edges[k + 32]);
        int p3 = __ldg(&g_edges[k + 48]);
        float2 x0 = __ldg(&g_xs[p0]);
        float2 x1 = __ldg(&g_xs[p1]);
        float2 x2 = __ldg(&g_xs[p2]);
        float2 x3 = __ldg(&g_xs[p3]);
        s0 += x0.x + x1.x + x2.x + x3.x;
        s1 += x0.y + x1.y + x2.y + x3.y;
    }
    for (; k < end; k += 16) {
        float2 xv = __ldg(&g_xs[__ldg(&g_edges[k])]);
        s0 += xv.x; s1 += xv.y;
    }
#pragma unroll
    for (int o = 8; o; o >>= 1) {
        s0 += __shfl_xor_sync(0xffffffffu, s0, o, 16);
        s1 += __shfl_xor_sync(0xffffffffu, s1, o, 16);
    }
    float di = g_dinv[node];
    float2 xn = __ldg(&g_xs[node]);   // xn = x*di already
    // u = di*(S + x'[node])  =>  di*S + x*di^2
    s0 = di * (s0 + xn.x);
    s1 = di * (s1 + xn.y);
    int c0 = q * 4;
    float4 r;
    r.x = fmaxf(s0 * W1s[c0 + 0] + s1 * W1s[HID + c0 + 0] + b1s[c0 + 0], 0.f);
    r.y = fmaxf(s0 * W1s[c0 + 1] + s1 * W1s[HID + c0 + 1] + b1s[c0 + 1], 0.f);
    r.z = fmaxf(s0 * W1s[c0 + 2] + s1 * W1s[HID + c0 + 2] + b1s[c0 + 2], 0.f);
    r.w = fmaxf(s0 * W1s[c0 + 3] + s1 * W1s[HID + c0 + 3] + b1s[c0 + 3], 0.f);
    r.x *= di; r.y *= di; r.z *= di; r.w *= di;   // pre-scale for next layer
    store_h4(hout + (size_t)node * HID + c0, r);
}

// ---------------- fp16 row gather ----------------
__device__ __forceinline__ float4 gather_h4(const __half* __restrict__ t, int row, int q) {
    uint2 raw = __ldg((const uint2*)(t + ((size_t)row << 6) + (q << 2)));
    float2 a = __half22float2(*(__half2*)&raw.x);
    float2 b = __half22float2(*(__half2*)&raw.y);
    return make_float4(a.x, a.y, b.x, b.y);
}

#define ADD4(v) { acc.x += (v).x; acc.y += (v).y; acc.z += (v).z; acc.w += (v).w; }

// Aggregation core: u = di*(sum t'[s] + t'[node]).
// Edge indices loaded as int4 broadcasts (16B aligned via scalar prologue).
__device__ __forceinline__ float4 agg_core(const __half* __restrict__ t, int node, int q,
                                           float di) {
    float4 acc = gather_h4(t, node, q);      // t'[node]
    int beg = __ldg(&g_off[node]), end = __ldg(&g_off[node + 1]);
    int k = beg;
    // align k to 4-int (16B) boundary
    for (; k < end && (k & 3); k++) {
        float4 v = gather_h4(t, __ldg(&g_edges[k]), q);
        ADD4(v);
    }
    for (; k + 8 <= end; k += 8) {
        int4 e0 = __ldg((const int4*)&g_edges[k]);
        int4 e1 = __ldg((const int4*)&g_edges[k + 4]);
        float4 v0 = gather_h4(t, e0.x, q);
        float4 v1 = gather_h4(t, e0.y, q);
        float4 v2 = gather_h4(t, e0.z, q);
        float4 v3 = gather_h4(t, e0.w, q);
        float4 v4 = gather_h4(t, e1.x, q);
        float4 v5 = gather_h4(t, e1.y, q);
        float4 v6 = gather_h4(t, e1.z, q);
        float4 v7 = gather_h4(t, e1.w, q);
        ADD4(v0); ADD4(v1); ADD4(v2); ADD4(v3);
        ADD4(v4); ADD4(v5); ADD4(v6); ADD4(v7);
    }
    if (k + 4 <= end) {
        int4 e0 = __ldg((const int4*)&g_edges[k]);
        float4 v0 = gather_h4(t, e0.x, q);
        float4 v1 = gather_h4(t, e0.y, q);
        float4 v2 = gather_h4(t, e0.z, q);
        float4 v3 = gather_h4(t, e0.w, q);
        ADD4(v0); ADD4(v1); ADD4(v2); ADD4(v3);
        k += 4;
    }
    for (; k < end; k++) {
        float4 v = gather_h4(t, __ldg(&g_edges[k]), q);
        ADD4(v);
    }
    acc.x *= di; acc.y *= di; acc.z *= di; acc.w *= di;
    return acc;
}

// Warp-level 64x64 matmul: per-node u lives in 16 lanes' float4; broadcast via shfl.
__device__ __forceinline__ float4 warp_matmul(float4 acc, const float* __restrict__ Ws,
                                              const float* __restrict__ bs, int q) {
    float a[4] = {acc.x, acc.y, acc.z, acc.w};
    int c0 = q * 4;
    float4 o = make_float4(bs[c0], bs[c0 + 1], bs[c0 + 2], bs[c0 + 3]);
#pragma unroll
    for (int k = 0; k < HID; k++) {
        float hk = __shfl_sync(0xffffffffu, a[k & 3], k >> 2, 16);
        float4 w = *(const float4*)&Ws[k * HID + c0];
        o.x += hk * w.x; o.y += hk * w.y; o.z += hk * w.z; o.w += hk * w.w;
    }
    o.x = fmaxf(o.x, 0.f); o.y = fmaxf(o.y, 0.f);
    o.z = fmaxf(o.z, 0.f); o.w = fmaxf(o.w, 0.f);
    return o;
}

// ---------------- fused layer: out = relu(u @ W + b) * dinv (for next gather) ----------------
__global__ void __launch_bounds__(512) k_layer(const __half* __restrict__ tin,
                                               const float* __restrict__ W,
                                               const float* __restrict__ b,
                                               __half* __restrict__ tout) {
    __shared__ float Ws[HID * HID];
    __shared__ float bs[HID];
    int tid = threadIdx.x;
    for (int i = tid; i < HID * HID; i += 512) Ws[i] = W[i];
    if (tid < HID) bs[tid] = b[tid];
    __syncthreads();
    int q = tid & 15;
    int node = blockIdx.x * 32 + (tid >> 4);
    if (node >= NN) return;
    float di = g_dinv[node];
    float4 acc = agg_core(tin, node, q, di);
    float4 o = warp_matmul(acc, Ws, bs, q);
    o.x *= di; o.y *= di; o.z *= di; o.w *= di;   // pre-scale for next layer
    store_h4(tout + (size_t)node * HID + q * 4, o);
}

// Layer-3 variant: plain h into the mean-pool accumulators.
__global__ void __launch_bounds__(512) k_layer_pool(const __half* __restrict__ tin,
                                                    const float* __restrict__ W,
                                                    const float* __restrict__ b,
                                                    const int* __restrict__ batch) {
    __shared__ float Ws[HID * HID];
    __shared__ float bs[HID];
    int tid = threadIdx.x;
    for (int i = tid; i < HID * HID; i += 512) Ws[i] = W[i];
    if (tid < HID) bs[tid] = b[tid];
    __syncthreads();
    int q = tid & 15;
    int node = blockIdx.x * 32 + (tid >> 4);
    if (node >= NN) return;
    float di = g_dinv[node];
    float4 acc = agg_core(tin, node, q, di);
    float4 o = warp_matmul(acc, Ws, bs, q);
    int g = batch[node];
    red_add_v4(g_pool + (size_t)g * HID + q * 4, o);
    if (q == 0) atomicAdd(&g_cnt[g], 1.0f);
}

// ---------------- per-graph MLP + sigmoid ----------------
__global__ void k_mlp(const float* __restrict__ lw1, const float* __restrict__ lb1,
                      const float* __restrict__ lw2, const float* __restrict__ lb2,
                      float* __restrict__ out) {
    __shared__ float w1s[HID * 32];
    __shared__ float b1s[32];
    __shared__ float w2s[32];
    int tid = threadIdx.x;
    for (int idx = tid; idx < HID * 32; idx += 128) w1s[idx] = lw1[idx];
    if (tid < 32) { b1s[tid] = lb1[tid]; w2s[tid] = lw2[tid]; }
    __syncthreads();
    int g = blockIdx.x * 128 + tid;
    if (g >= NG) return;
    float inv = 1.0f / fmaxf(g_cnt[g], 1.0f);
    float p[HID];
#pragma unroll
    for (int c = 0; c < HID; c++) p[c] = g_pool[g * HID + c] * inv;
    float z = lb2[0];
    for (int j = 0; j < 32; j++) {
        float a = b1s[j];
#pragma unroll
        for (int c = 0; c < HID; c++) a += p[c] * w1s[c * 32 + j];
        a = a > 0.f ? a : 0.f;
        z += a * w2s[j];
    }
    out[g] = 1.0f / (1.0f + expf(-z));
}

extern "C" void kernel_launch(void* const* d_in, const int* in_sizes, int n_in,
                              void* d_out, int out_size) {
    // Size-driven input identification (robust to metadata ordering).
    const float *x = 0, *W1 = 0, *b1 = 0, *W2 = 0, *b2 = 0, *W3 = 0, *b3 = 0;
    const float *lw1 = 0, *lb1 = 0, *lw2 = 0, *lb2 = 0;
    const int *ei = 0, *batch = 0;
    int nW = 0, nb = 0, n32 = 0;
    for (int i = 0; i < n_in; i++) {
        int sz = in_sizes[i];
        const void* p = d_in[i];
        switch (sz) {
            case 300000:  x = (const float*)p; break;
            case 2500000: ei = (const int*)p; break;
            case 150000:  batch = (const int*)p; break;
            case 128:     W1 = (const float*)p; break;
            case 4096:    if (nW++ == 0) W2 = (const float*)p; else W3 = (const float*)p; break;
            case 64:      if (nb == 0) b1 = (const float*)p;
                          else if (nb == 1) b2 = (const float*)p;
                          else b3 = (const float*)p;
                          nb++; break;
            case 2048:    lw1 = (const float*)p; break;
            case 32:      if (n32++ == 0) lb1 = (const float*)p; else lw2 = (const float*)p; break;
            case 1:       lb2 = (const float*)p; break;
        }
    }
    float* out = (float*)d_out;

    __half *gT0, *gT1;
    int *gIndeg;
    cudaGetSymbolAddress((void**)&gT0, g_T0);
    cudaGetSymbolAddress((void**)&gT1, g_T1);
    cudaGetSymbolAddress((void**)&gIndeg, g_indeg);

    const int TB = 256;
    // only indeg needs pre-zeroing (pool/cnt zeroed in ps3)
    cudaMemsetAsync(gIndeg, 0, NN * sizeof(int));

    // degree + CSR build (dst-bucketed, src-only records)
    k_deg_accum<<<(NE + TB - 1) / TB, TB>>>(ei);
    k_ps1 <<<PS_NB, PS_B>>>(x);
    k_ps2 <<<1, PS_B>>>();
    k_ps3 <<<PS_NB, PS_B>>>();
    k_fill<<<(NE + TB - 1) / TB, TB>>>(ei);

    // layer 1: aggregate x', fused W1+bias+relu -> h1' (fp16, pre-scaled)
    k_aggr_x<<<(NN * 16 + TB - 1) / TB, TB>>>(W1, b1, gT0);

    // layer 2 fused
    k_layer<<<(NN + 31) / 32, 512>>>(gT0, W2, b2, gT1);

    // layer 3 fused + pooled
    k_layer_pool<<<(NN + 31) / 32, 512>>>(gT1, W3, b3, batch);

    // MLP head
    k_mlp<<<(NG + 127) / 128, 128>>>(lw1, lb1, lw2, lb2, out);
}